// round 4
// baseline (speedup 1.0000x reference)
#include <cuda_runtime.h>

// Direct (reference-faithful) GCN pipeline.
// deg -> CSR(dst) -> h0 -> 3x [ h@W ; CSR-aggregate with sym-norm + self-loop + bias ]
// -> pool per graph -> tanh MLP head.

#define NN 50000
#define NE 1600000
#define ED 128
#define NG 32

__device__ int   g_cnt[NN];          // in-degree (edges only)
__device__ int   g_off[NN + 1];      // CSR row offsets
__device__ int   g_cur[NN];          // fill cursors
__device__ int   g_col[NE];          // CSR column (src node) ids
__device__ float g_dinv[NN];
__device__ float g_ha[NN * ED];      // feature buffer A
__device__ float g_hb[NN * ED];      // feature buffer B
__device__ float g_pooled[NG * ED];

// ---------------------------------------------------------------------------
__global__ void k_zero_cnt() {
    int i = blockIdx.x * blockDim.x + threadIdx.x;
    if (i < NN) g_cnt[i] = 0;
    if (i < NG * ED) g_pooled[i] = 0.0f;
}

__global__ void k_count(const int* __restrict__ dst) {
    int e = blockIdx.x * blockDim.x + threadIdx.x;
    if (e < NE) atomicAdd(&g_cnt[dst[e]], 1);
}

__global__ void k_dinv() {
    int i = blockIdx.x * blockDim.x + threadIdx.x;
    if (i < NN) g_dinv[i] = rsqrtf((float)(g_cnt[i] + 1));   // +1 self-loop
}

// single-block exclusive scan of g_cnt into g_off / g_cur
__global__ void k_scan() {
    __shared__ int part[1024];
    __shared__ int spart[1024];
    const int T = 1024;
    const int C = (NN + T - 1) / T;       // 49
    int t = threadIdx.x;
    int lo = t * C;
    int hi = min(lo + C, NN);
    int s = 0;
    for (int i = lo; i < hi; i++) s += g_cnt[i];
    part[t] = s;
    __syncthreads();
    // exclusive scan of part[] (Hillis-Steele)
    int v = part[t];
    for (int o = 1; o < T; o <<= 1) {
        spart[t] = v;
        __syncthreads();
        if (t >= o) v += spart[t - o];
        __syncthreads();
    }
    int excl = v - part[t];
    int run = excl;
    for (int i = lo; i < hi; i++) {
        g_off[i] = run;
        g_cur[i] = run;
        run += g_cnt[i];
    }
    if (t == T - 1) g_off[NN] = run;
}

__global__ void k_fill(const int* __restrict__ src, const int* __restrict__ dst) {
    int e = blockIdx.x * blockDim.x + threadIdx.x;
    if (e >= NE) return;
    int p = atomicAdd(&g_cur[dst[e]], 1);
    g_col[p] = src[e];
}

// h0[i][j] = x[i]*lin_w[j] + lin_b[j]
__global__ void k_h0(const float* __restrict__ x,
                     const float* __restrict__ lin_w, const float* __restrict__ lin_b) {
    int j = threadIdx.x;
    float w = lin_w[j], b = lin_b[j];
    for (int i = blockIdx.x; i < NN; i += gridDim.x)
        g_ha[i * ED + j] = fmaf(x[i], w, b);
}

// hb = ha @ W   (128 threads = cols, 32 rows per block, row-tiled in smem)
#define GROWS 32
__global__ void k_gemm(const float* __restrict__ W) {
    __shared__ float sa[GROWS][ED];
    int j = threadIdx.x;
    int r0 = blockIdx.x * GROWS;
    int nr = min(GROWS, NN - r0);

    for (int r = 0; r < nr; r++) sa[r][j] = g_ha[(r0 + r) * ED + j];
    __syncthreads();

    float acc[GROWS];
    #pragma unroll
    for (int r = 0; r < GROWS; r++) acc[r] = 0.0f;

    for (int i = 0; i < ED; i++) {
        float w = __ldg(&W[i * ED + j]);
        #pragma unroll
        for (int r = 0; r < GROWS; r++) acc[r] = fmaf(sa[r][i], w, acc[r]);
    }
    for (int r = 0; r < nr; r++) g_hb[(r0 + r) * ED + j] = acc[r];
}

// ha[d] = dinv[d]^2 * hb[d] + sum_{s in row d} dinv[d]*dinv[s]*hb[s] + bias
__global__ void k_agg(const float* __restrict__ bias) {
    int gt = blockIdx.x * blockDim.x + threadIdx.x;
    int node = gt >> 5;
    int lane = gt & 31;
    if (node >= NN) return;

    float dd = g_dinv[node];
    const float* hn = g_hb + node * ED;
    float w0 = dd * dd;
    float a0 = w0 * hn[lane];
    float a1 = w0 * hn[lane + 32];
    float a2 = w0 * hn[lane + 64];
    float a3 = w0 * hn[lane + 96];

    int p0 = g_off[node], p1 = g_off[node + 1];
    for (int p = p0; p < p1; p++) {
        int s = g_col[p];
        float w = dd * g_dinv[s];
        const float* hs = g_hb + s * ED;
        a0 = fmaf(w, hs[lane],      a0);
        a1 = fmaf(w, hs[lane + 32], a1);
        a2 = fmaf(w, hs[lane + 64], a2);
        a3 = fmaf(w, hs[lane + 96], a3);
    }
    float* ho = g_ha + node * ED;
    ho[lane]      = a0 + bias[lane];
    ho[lane + 32] = a1 + bias[lane + 32];
    ho[lane + 64] = a2 + bias[lane + 64];
    ho[lane + 96] = a3 + bias[lane + 96];
}

// pool per graph: block of 128 threads (j = feature), 512 rows per block
#define PROWS 512
__global__ void k_pool(const int* __restrict__ batch) {
    __shared__ float sh[NG][ED];
    int j = threadIdx.x;
    for (int g = 0; g < NG; g++) sh[g][j] = 0.0f;
    __syncthreads();
    int r0 = blockIdx.x * PROWS;
    int r1 = min(r0 + PROWS, NN);
    for (int r = r0; r < r1; r++) {
        int g = batch[r];
        sh[g][j] += g_ha[r * ED + j];
    }
    __syncthreads();
    for (int g = 0; g < NG; g++)
        atomicAdd(&g_pooled[g * ED + j], sh[g][j]);
}

// head: hr = tanh(pooled @ r1_w + r1_b); out = hr @ r2_w + r2_b
__global__ void k_head(const float* __restrict__ r1_w, const float* __restrict__ r1_b,
                       const float* __restrict__ r2_w, const float* __restrict__ r2_b,
                       float* __restrict__ out) {
    __shared__ float sp[NG][ED];
    __shared__ float hr[NG][ED];
    int j = threadIdx.x;
    for (int g = 0; g < NG; g++) sp[g][j] = g_pooled[g * ED + j];
    __syncthreads();
    float bj = r1_b[j];
    for (int g = 0; g < NG; g++) {
        float acc = bj;
        #pragma unroll 8
        for (int i = 0; i < ED; i++) acc = fmaf(sp[g][i], r1_w[i * ED + j], acc);
        hr[g][j] = tanhf(acc);
    }
    __syncthreads();
    int warp = j >> 5, lane = j & 31;
    for (int g = warp; g < NG; g += 4) {
        float s = hr[g][lane]      * r2_w[lane]
                + hr[g][lane + 32] * r2_w[lane + 32]
                + hr[g][lane + 64] * r2_w[lane + 64]
                + hr[g][lane + 96] * r2_w[lane + 96];
        #pragma unroll
        for (int o = 16; o > 0; o >>= 1) s += __shfl_down_sync(0xffffffffu, s, o);
        if (lane == 0) out[g] = s + r2_b[0];
    }
}

// ---------------------------------------------------------------------------
extern "C" void kernel_launch(void* const* d_in, const int* in_sizes, int n_in,
                              void* d_out, int out_size) {
    const float* x     = (const float*)d_in[0];
    const int*   eidx  = (const int*)  d_in[1];
    const int*   batch = (const int*)  d_in[2];
    const float* lin_w = (const float*)d_in[3];
    const float* lin_b = (const float*)d_in[4];
    const float* gcn_w = (const float*)d_in[5];
    const float* gcn_b = (const float*)d_in[6];
    const float* r1_w  = (const float*)d_in[7];
    const float* r1_b  = (const float*)d_in[8];
    const float* r2_w  = (const float*)d_in[9];
    const float* r2_b  = (const float*)d_in[10];
    float* out = (float*)d_out;

    const int* src = eidx;          // edge_index[0]
    const int* dst = eidx + NE;     // edge_index[1]

    int nb = (NN + 255) / 256;
    int eb = (NE + 255) / 256;

    k_zero_cnt<<<nb, 256>>>();
    k_count<<<eb, 256>>>(dst);
    k_dinv<<<nb, 256>>>();
    k_scan<<<1, 1024>>>();
    k_fill<<<eb, 256>>>(src, dst);

    k_h0<<<2048, ED>>>(x, lin_w, lin_b);

    int gb = (NN + GROWS - 1) / GROWS;
    int ab = (NN * 32 + 255) / 256;
    for (int l = 0; l < 3; l++) {
        k_gemm<<<gb, ED>>>(gcn_w + l * ED * ED);
        k_agg<<<ab, 256>>>(gcn_b + l * ED);
    }

    k_pool<<<(NN + PROWS - 1) / PROWS, ED>>>(batch);
    k_head<<<1, ED>>>(r1_w, r1_b, r2_w, r2_b, out);
}

// round 5
// speedup vs baseline: 2.3197x; 2.3197x over previous
#include <cuda_runtime.h>

// ---------------------------------------------------------------------------
// PureGNN rank collapse: h_l = Z_l @ B_l with Z_l scalar basis columns
//   [P^l x, P^l 1, ..., P 1, 1], B_l chained from the dense weights.
// Only 6 scalar aggregations (P^k x, P^k 1, k=1..3) touch the graph.
// CRITICAL: __device__ globals are ONLY referenced inside device code
// (never passed as kernel args from host — ATS makes that silently wrong).
// ---------------------------------------------------------------------------

#define NN 50000
#define NE 1600000
#define NG 32
#define ED 128

__device__ float  g_deg [NN];
__device__ float  g_dinv[NN];
__device__ float2 g_z1  [NN];   // (P x,   P 1)
__device__ float2 g_z2  [NN];   // (P^2 x, P^2 1)
__device__ float2 g_z3  [NN];   // (P^3 x, P^3 1)
__device__ float  g_S   [NG * 5];

// ---------------------------------------------------------------------------
__global__ void k_init_deg() {
    int i = blockIdx.x * blockDim.x + threadIdx.x;
    if (i < NN) g_deg[i] = 1.0f;                 // self-loop
    if (i < NG * 5) g_S[i] = 0.0f;
}

__global__ void k_count(const int* __restrict__ dst) {
    int e = blockIdx.x * blockDim.x + threadIdx.x;
    if (e < NE) atomicAdd(&g_deg[dst[e]], 1.0f);
}

// dinv = rsqrt(deg); z1 self-loop init: z1[i] = dinv^2 * (x[i], 1)
__global__ void k_dinv_init1(const float* __restrict__ x) {
    int i = blockIdx.x * blockDim.x + threadIdx.x;
    if (i >= NN) return;
    float di = rsqrtf(g_deg[i]);
    g_dinv[i] = di;
    float w = di * di;
    g_z1[i] = make_float2(w * x[i], w);
}

// pass-1 edges: z1[d] += dinv[s]*dinv[d] * (x[s], 1)
__global__ void k_edge1(const int* __restrict__ src, const int* __restrict__ dst,
                        const float* __restrict__ x) {
    int e = blockIdx.x * blockDim.x + threadIdx.x;
    if (e >= NE) return;
    int s = src[e], d = dst[e];
    float w = __ldg(&g_dinv[s]) * __ldg(&g_dinv[d]);
    atomicAdd(&g_z1[d].x, w * __ldg(&x[s]));
    atomicAdd(&g_z1[d].y, w);
}

// self-loop init for pass P (2: z1->z2, 3: z2->z3): zout[i] = dinv^2 * zin[i]
template <int P>
__global__ void k_selfT() {
    const float2* __restrict__ zin  = (P == 2) ? g_z1 : g_z2;
    float2*       __restrict__ zout = (P == 2) ? g_z2 : g_z3;
    int i = blockIdx.x * blockDim.x + threadIdx.x;
    if (i >= NN) return;
    float di = g_dinv[i];
    float w = di * di;
    float2 v = zin[i];
    zout[i] = make_float2(w * v.x, w * v.y);
}

// edge pass P: zout[d] += dinv[s]*dinv[d] * zin[s]
template <int P>
__global__ void k_edgeT(const int* __restrict__ src, const int* __restrict__ dst) {
    const float2* __restrict__ zin  = (P == 2) ? g_z1 : g_z2;
    float2*       __restrict__ zout = (P == 2) ? g_z2 : g_z3;
    int e = blockIdx.x * blockDim.x + threadIdx.x;
    if (e >= NE) return;
    int s = src[e], d = dst[e];
    float w = __ldg(&g_dinv[s]) * __ldg(&g_dinv[d]);
    float2 v = __ldg(&zin[s]);
    atomicAdd(&zout[d].x, w * v.x);
    atomicAdd(&zout[d].y, w * v.y);
}

// per-graph pooling of the 5 scalar fields [z3.x, z3.y, z2.y, z1.y, 1]
__global__ void k_pool(const int* __restrict__ batch) {
    __shared__ float sh[NG * 5];
    for (int t = threadIdx.x; t < NG * 5; t += blockDim.x) sh[t] = 0.0f;
    __syncthreads();
    int i = blockIdx.x * blockDim.x + threadIdx.x;
    if (i < NN) {
        int g = batch[i];
        float2 a = g_z3[i];
        float2 b = g_z2[i];
        float2 c = g_z1[i];
        atomicAdd(&sh[g * 5 + 0], a.x);
        atomicAdd(&sh[g * 5 + 1], a.y);
        atomicAdd(&sh[g * 5 + 2], b.y);
        atomicAdd(&sh[g * 5 + 3], c.y);
        atomicAdd(&sh[g * 5 + 4], 1.0f);
    }
    __syncthreads();
    for (int t = threadIdx.x; t < NG * 5; t += blockDim.x)
        if (sh[t] != 0.0f) atomicAdd(&g_S[t], sh[t]);
}

// ---------------------------------------------------------------------------
// Readout: B3 = chained weights; pooled = S @ B3; tanh MLP head.
// Single block, 128 threads (thread j = feature column j).
// ---------------------------------------------------------------------------
__global__ void k_readout(const float* __restrict__ lin_w, const float* __restrict__ lin_b,
                          const float* __restrict__ gcn_w, const float* __restrict__ gcn_b,
                          const float* __restrict__ r1_w,  const float* __restrict__ r1_b,
                          const float* __restrict__ r2_w,  const float* __restrict__ r2_b,
                          float* __restrict__ out) {
    __shared__ float vin[5][ED];
    __shared__ float vout[5][ED];
    __shared__ float pooled[NG][ED];
    __shared__ float hr[NG][ED];
    __shared__ float sS[NG * 5];

    int j = threadIdx.x;   // 0..127

    vin[0][j] = lin_w[j];   // basis coefficient rows start as [lin_w; lin_b]
    vin[1][j] = lin_b[j];
    for (int t = j; t < NG * 5; t += ED) sS[t] = g_S[t];
    __syncthreads();

    int nrows = 2;
    for (int l = 0; l < 3; l++) {
        const float* W = gcn_w + l * ED * ED;
        for (int r = 0; r < nrows; r++) {
            float acc = 0.0f;
            #pragma unroll 8
            for (int i = 0; i < ED; i++) acc = fmaf(vin[r][i], W[i * ED + j], acc);
            vout[r][j] = acc;
        }
        vout[nrows][j] = gcn_b[l * ED + j];
        nrows++;
        __syncthreads();
        for (int r = 0; r < nrows; r++) vin[r][j] = vout[r][j];
        __syncthreads();
    }
    // vin rows (5) correspond to basis [P^3x, P^3 1, P^2 1, P 1, 1] == S columns

    for (int g = 0; g < NG; g++) {
        float p = 0.0f;
        #pragma unroll
        for (int r = 0; r < 5; r++) p = fmaf(sS[g * 5 + r], vin[r][j], p);
        pooled[g][j] = p;
    }
    __syncthreads();

    float bj = r1_b[j];
    for (int g = 0; g < NG; g++) {
        float acc = bj;
        #pragma unroll 8
        for (int i = 0; i < ED; i++) acc = fmaf(pooled[g][i], r1_w[i * ED + j], acc);
        hr[g][j] = tanhf(acc);
    }
    __syncthreads();

    int warp = j >> 5, lane = j & 31;
    for (int g = warp; g < NG; g += 4) {
        float s = hr[g][lane]      * r2_w[lane]
                + hr[g][lane + 32] * r2_w[lane + 32]
                + hr[g][lane + 64] * r2_w[lane + 64]
                + hr[g][lane + 96] * r2_w[lane + 96];
        #pragma unroll
        for (int o = 16; o > 0; o >>= 1) s += __shfl_down_sync(0xffffffffu, s, o);
        if (lane == 0) out[g] = s + r2_b[0];
    }
}

// ---------------------------------------------------------------------------
extern "C" void kernel_launch(void* const* d_in, const int* in_sizes, int n_in,
                              void* d_out, int out_size) {
    const float* x     = (const float*)d_in[0];
    const int*   eidx  = (const int*)  d_in[1];
    const int*   batch = (const int*)  d_in[2];
    const float* lin_w = (const float*)d_in[3];
    const float* lin_b = (const float*)d_in[4];
    const float* gcn_w = (const float*)d_in[5];
    const float* gcn_b = (const float*)d_in[6];
    const float* r1_w  = (const float*)d_in[7];
    const float* r1_b  = (const float*)d_in[8];
    const float* r2_w  = (const float*)d_in[9];
    const float* r2_b  = (const float*)d_in[10];
    float* out = (float*)d_out;

    const int* src = eidx;          // edge_index[0]
    const int* dst = eidx + NE;     // edge_index[1]

    int nb = (NN + 255) / 256;
    int eb = (NE + 255) / 256;

    k_init_deg<<<nb, 256>>>();
    k_count<<<eb, 256>>>(dst);
    k_dinv_init1<<<nb, 256>>>(x);

    k_edge1<<<eb, 256>>>(src, dst, x);      // z1 = P [x, 1]

    k_selfT<2><<<nb, 256>>>();
    k_edgeT<2><<<eb, 256>>>(src, dst);      // z2 = P z1

    k_selfT<3><<<nb, 256>>>();
    k_edgeT<3><<<eb, 256>>>(src, dst);      // z3 = P z2

    k_pool<<<nb, 256>>>(batch);
    k_readout<<<1, ED>>>(lin_w, lin_b, gcn_w, gcn_b, r1_w, r1_b, r2_w, r2_b, out);
}

// round 6
// speedup vs baseline: 5.8283x; 2.5126x over previous
#include <cuda_runtime.h>

// ---------------------------------------------------------------------------
// PureGNN rank collapse, u-scaled form:
//   u_k = dinv .* z_k ;  edge pass: acc[d] += u_k[s]  (no weights in edge loop)
//   node pass: z_{k+1} = dinv .* (acc + u_k);  u_{k+1} = dinv .* z_{k+1}
// Basis after 3 layers: [P^3 x, P^3 1, P^2 1, P 1, 1].
// RULE: __device__ globals referenced ONLY inside device code (ATS trap).
// ---------------------------------------------------------------------------

#define NN 50000
#define NE 1600000
#define NG 32
#define ED 128

__device__ float  g_deg [NN];
__device__ float  g_dinv[NN];
__device__ float2 g_u   [NN];     // current u_k
__device__ float2 g_acc [NN];     // edge accumulator
__device__ float  g_k1y [NN];     // z1.y
__device__ float  g_k2y [NN];     // z2.y
__device__ float  g_S   [NG * 5];

// ---------------------------------------------------------------------------
__global__ void k_init() {
    int i = blockIdx.x * blockDim.x + threadIdx.x;
    if (i < NN) g_deg[i] = 1.0f;                  // self-loop
    if (i < NG * 5) g_S[i] = 0.0f;
}

// 4 edges per thread, vectorized index load
__global__ void k_count(const int* __restrict__ dst) {
    int e = (blockIdx.x * blockDim.x + threadIdx.x) * 4;
    if (e + 3 < NE) {
        int4 d4 = *(const int4*)(dst + e);
        atomicAdd(&g_deg[d4.x], 1.0f);
        atomicAdd(&g_deg[d4.y], 1.0f);
        atomicAdd(&g_deg[d4.z], 1.0f);
        atomicAdd(&g_deg[d4.w], 1.0f);
    } else {
        for (; e < NE; e++) atomicAdd(&g_deg[dst[e]], 1.0f);
    }
}

// dinv, u0 = dinv * (x, 1), acc = 0
__global__ void k_prep(const float* __restrict__ x) {
    int i = blockIdx.x * blockDim.x + threadIdx.x;
    if (i >= NN) return;
    float di = rsqrtf(g_deg[i]);
    g_dinv[i] = di;
    g_u[i]   = make_float2(di * x[i], di);
    g_acc[i] = make_float2(0.0f, 0.0f);
}

// edge pass: acc[d] += u[s]   (2 edges/thread, float2 vector atomic)
__global__ void k_edge(const int* __restrict__ src, const int* __restrict__ dst) {
    int e = (blockIdx.x * blockDim.x + threadIdx.x) * 2;
    if (e + 1 < NE) {
        int2 s2 = *(const int2*)(src + e);
        int2 d2 = *(const int2*)(dst + e);
        float2 v0 = __ldg(&g_u[s2.x]);
        float2 v1 = __ldg(&g_u[s2.y]);
        atomicAdd(&g_acc[d2.x], v0);
        atomicAdd(&g_acc[d2.y], v1);
    } else if (e < NE) {
        atomicAdd(&g_acc[dst[e]], __ldg(&g_u[src[e]]));
    }
}

// node pass K (1 or 2): z = dinv*(acc+u); keep z.y; u = dinv*z; acc = 0
template <int K>
__global__ void k_node() {
    int i = blockIdx.x * blockDim.x + threadIdx.x;
    if (i >= NN) return;
    float di = g_dinv[i];
    float2 a = g_acc[i];
    float2 u = g_u[i];
    float zx = di * (a.x + u.x);
    float zy = di * (a.y + u.y);
    if (K == 1) g_k1y[i] = zy;
    else        g_k2y[i] = zy;
    g_u[i]   = make_float2(di * zx, di * zy);
    g_acc[i] = make_float2(0.0f, 0.0f);
}

// node pass 3 fused with per-graph pooling (batch is sorted -> warp-uniform fast path)
__global__ void k_node3_pool(const int* __restrict__ batch) {
    __shared__ float sh[NG * 5];
    for (int t = threadIdx.x; t < NG * 5; t += blockDim.x) sh[t] = 0.0f;
    __syncthreads();

    int i = blockIdx.x * blockDim.x + threadIdx.x;
    bool act = (i < NN);
    float z3x = 0.0f, z3y = 0.0f, k2 = 0.0f, k1 = 0.0f;
    int g = 0;
    if (act) {
        float di = g_dinv[i];
        float2 a = g_acc[i];
        float2 u = g_u[i];
        z3x = di * (a.x + u.x);
        z3y = di * (a.y + u.y);
        k2  = g_k2y[i];
        k1  = g_k1y[i];
        g   = batch[i];
    }
    unsigned m = __ballot_sync(0xffffffffu, act);
    int lane = threadIdx.x & 31;
    if (m == 0xffffffffu) {
        int g0 = __shfl_sync(0xffffffffu, g, 0);
        if (__all_sync(0xffffffffu, g == g0)) {
            #pragma unroll
            for (int o = 16; o > 0; o >>= 1) {
                z3x += __shfl_down_sync(0xffffffffu, z3x, o);
                z3y += __shfl_down_sync(0xffffffffu, z3y, o);
                k2  += __shfl_down_sync(0xffffffffu, k2,  o);
                k1  += __shfl_down_sync(0xffffffffu, k1,  o);
            }
            if (lane == 0) {
                atomicAdd(&sh[g0 * 5 + 0], z3x);
                atomicAdd(&sh[g0 * 5 + 1], z3y);
                atomicAdd(&sh[g0 * 5 + 2], k2);
                atomicAdd(&sh[g0 * 5 + 3], k1);
                atomicAdd(&sh[g0 * 5 + 4], 32.0f);
            }
        } else {
            atomicAdd(&sh[g * 5 + 0], z3x);
            atomicAdd(&sh[g * 5 + 1], z3y);
            atomicAdd(&sh[g * 5 + 2], k2);
            atomicAdd(&sh[g * 5 + 3], k1);
            atomicAdd(&sh[g * 5 + 4], 1.0f);
        }
    } else if (act) {
        atomicAdd(&sh[g * 5 + 0], z3x);
        atomicAdd(&sh[g * 5 + 1], z3y);
        atomicAdd(&sh[g * 5 + 2], k2);
        atomicAdd(&sh[g * 5 + 3], k1);
        atomicAdd(&sh[g * 5 + 4], 1.0f);
    }
    __syncthreads();
    for (int t = threadIdx.x; t < NG * 5; t += blockDim.x)
        if (sh[t] != 0.0f) atomicAdd(&g_S[t], sh[t]);
}

// ---------------------------------------------------------------------------
// Readout: 512 threads. grp = tid/128 (0..3), j = tid%128.
// Chain rows spread over grps; head graphs spread over grps (8 each).
// ---------------------------------------------------------------------------
__global__ void k_readout(const float* __restrict__ lin_w, const float* __restrict__ lin_b,
                          const float* __restrict__ gcn_w, const float* __restrict__ gcn_b,
                          const float* __restrict__ r1_w,  const float* __restrict__ r1_b,
                          const float* __restrict__ r2_w,  const float* __restrict__ r2_b,
                          float* __restrict__ out) {
    __shared__ float vin[5][ED];
    __shared__ float vout[5][ED];
    __shared__ float pooled[NG][ED];
    __shared__ float hr[NG][ED];
    __shared__ float sS[NG * 5];

    int tid = threadIdx.x;
    int j   = tid & 127;
    int grp = tid >> 7;      // 0..3

    if (grp == 0) { vin[0][j] = lin_w[j]; vin[1][j] = lin_b[j]; }
    for (int t = tid; t < NG * 5; t += 512) sS[t] = g_S[t];
    __syncthreads();

    int nrows = 2;
    for (int l = 0; l < 3; l++) {
        const float* W = gcn_w + l * ED * ED;
        if (grp < nrows) {
            float a0 = 0.0f, a1 = 0.0f;
            #pragma unroll 4
            for (int i = 0; i < ED; i += 2) {
                a0 = fmaf(vin[grp][i],     W[i * ED + j],       a0);
                a1 = fmaf(vin[grp][i + 1], W[(i + 1) * ED + j], a1);
            }
            vout[grp][j] = a0 + a1;
        }
        if (grp == 0) vout[nrows][j] = gcn_b[l * ED + j];
        nrows++;
        __syncthreads();
        for (int r = grp; r < nrows; r += 4) vin[r][j] = vout[r][j];
        __syncthreads();
    }
    // vin rows (5): [P^3x, P^3 1, P^2 1, P 1, 1] == S columns

    for (int g = grp * 8; g < grp * 8 + 8; g++) {
        float p = 0.0f;
        #pragma unroll
        for (int r = 0; r < 5; r++) p = fmaf(sS[g * 5 + r], vin[r][j], p);
        pooled[g][j] = p;
    }
    __syncthreads();

    float bj = r1_b[j];
    for (int g = grp * 8; g < grp * 8 + 8; g++) {
        float a0 = bj, a1 = 0.0f, a2 = 0.0f, a3 = 0.0f;
        #pragma unroll 2
        for (int i = 0; i < ED; i += 4) {
            a0 = fmaf(pooled[g][i],     r1_w[i * ED + j],       a0);
            a1 = fmaf(pooled[g][i + 1], r1_w[(i + 1) * ED + j], a1);
            a2 = fmaf(pooled[g][i + 2], r1_w[(i + 2) * ED + j], a2);
            a3 = fmaf(pooled[g][i + 3], r1_w[(i + 3) * ED + j], a3);
        }
        hr[g][j] = tanhf((a0 + a1) + (a2 + a3));
    }
    __syncthreads();

    int warp = tid >> 5;      // 0..15
    int lane = tid & 31;
    for (int g = warp; g < NG; g += 16) {
        float s = hr[g][lane]      * r2_w[lane]
                + hr[g][lane + 32] * r2_w[lane + 32]
                + hr[g][lane + 64] * r2_w[lane + 64]
                + hr[g][lane + 96] * r2_w[lane + 96];
        #pragma unroll
        for (int o = 16; o > 0; o >>= 1) s += __shfl_down_sync(0xffffffffu, s, o);
        if (lane == 0) out[g] = s + r2_b[0];
    }
}

// ---------------------------------------------------------------------------
extern "C" void kernel_launch(void* const* d_in, const int* in_sizes, int n_in,
                              void* d_out, int out_size) {
    const float* x     = (const float*)d_in[0];
    const int*   eidx  = (const int*)  d_in[1];
    const int*   batch = (const int*)  d_in[2];
    const float* lin_w = (const float*)d_in[3];
    const float* lin_b = (const float*)d_in[4];
    const float* gcn_w = (const float*)d_in[5];
    const float* gcn_b = (const float*)d_in[6];
    const float* r1_w  = (const float*)d_in[7];
    const float* r1_b  = (const float*)d_in[8];
    const float* r2_w  = (const float*)d_in[9];
    const float* r2_b  = (const float*)d_in[10];
    float* out = (float*)d_out;

    const int* src = eidx;          // edge_index[0]
    const int* dst = eidx + NE;     // edge_index[1]

    int nb = (NN + 255) / 256;
    int cb = (NE / 4 + 255) / 256;
    int eb = (NE / 2 + 255) / 256;

    k_init <<<nb, 256>>>();
    k_count<<<cb, 256>>>(dst);
    k_prep <<<nb, 256>>>(x);

    k_edge<<<eb, 256>>>(src, dst);       // acc1 = A u0
    k_node<1><<<nb, 256>>>();            // z1, u1

    k_edge<<<eb, 256>>>(src, dst);       // acc2 = A u1
    k_node<2><<<nb, 256>>>();            // z2, u2

    k_edge<<<eb, 256>>>(src, dst);       // acc3 = A u2
    k_node3_pool<<<nb, 256>>>(batch);    // z3 + pool

    k_readout<<<1, 512>>>(lin_w, lin_b, gcn_w, gcn_b, r1_w, r1_b, r2_w, r2_b, out);
}